// round 10
// baseline (speedup 1.0000x reference)
#include <cuda_runtime.h>

#define CK __restrict__
typedef unsigned long long ull;

// ---------------- f32x2 helpers (packed fp32 pipe, sm_103a) ----------------
__device__ __forceinline__ ull pack2(float lo, float hi) {
    ull r; asm("mov.b64 %0, {%1, %2};" : "=l"(r) : "f"(lo), "f"(hi)); return r;
}
__device__ __forceinline__ void unpack2(ull v, float& lo, float& hi) {
    asm("mov.b64 {%0, %1}, %2;" : "=f"(lo), "=f"(hi) : "l"(v));
}
__device__ __forceinline__ void ffma2(ull& d, ull a, ull b) {
    asm("fma.rn.f32x2 %0, %1, %2, %0;" : "+l"(d) : "l"(a), "l"(b));
}
__device__ __forceinline__ ull mul2(ull a, ull b) {
    ull r; asm("mul.rn.f32x2 %0, %1, %2;" : "=l"(r) : "l"(a), "l"(b)); return r;
}
__device__ __forceinline__ ull add2(ull a, ull b) {
    ull r; asm("add.rn.f32x2 %0, %1, %2;" : "=l"(r) : "l"(a), "l"(b)); return r;
}

// ---------------- scratch (device globals: allocation-free) ----------------
__device__ float g_y [4*128*128*128];                 // deconv output (incl. bias)
__device__ float g_kf[4*9*128*128];                   // PAC gaussian factors
__device__ __align__(16) float g_w1d[4*256*128*4*2];  // w1 repacked+dup: [p][ci][co][tap][2]
__device__ __align__(16) float g_w2d[128*9*128*2];    // wk repacked+dup: [c][ij][o][2]

// ---------------- weight prep ----------------
__global__ void prep_weights_kernel(const float* CK w1, const float* CK w2) {
    int idx = blockIdx.x * blockDim.x + threadIdx.x;
    const int n1 = 4*256*128*4;
    if (idx < n1) {
        int t  = idx & 3;
        int co = (idx >> 2) & 127;
        int ci = (idx >> 9) & 255;
        int p  = idx >> 17;
        int pr = p >> 1, ps = p & 1;
        int th = t >> 1, tw = t & 1;
        int kh = 2*th + 1 - pr;
        int kw = 2*tw + 1 - ps;
        float v = w1[((ci*128 + co)*4 + kh)*4 + kw];
        g_w1d[idx*2]   = v;   // duplicated pair for f32x2 broadcast
        g_w1d[idx*2+1] = v;
    }
    const int n2 = 128*9*128;
    if (idx < n2) {
        int o  = idx & 127;
        int ij = (idx >> 7) % 9;
        int c  = idx / (9*128);
        int i = ij / 3, j = ij % 3;
        float v = w2[((c*128 + o)*3 + (2 - i))*3 + (2 - j)];  // wk[o,c,i,j]=w2[c,o,2-i,2-j]
        g_w2d[idx*2]   = v;
        g_w2d[idx*2+1] = v;
    }
}

// ---------------- stage 1: conv_transpose 4x4 s2 p1 (f32x2, LDS.128) ----------------
// Per parity class (pr,ps): effective 2x2 stride-1 conv on the 64x64 input.
// Block: 32 co x (8R x 32S). Thread: 4co x 8sp (4 f32x2 pairs) -> acc 16 ull.
static const int DC_X_STRIDE = 36;
static const int DC_XC_BYTES = 16*9*DC_X_STRIDE*4;   // 20736 per copy
static const int DC_WS_BYTES = 16*32*4*8;            // 16384 (ull pairs, 32 co)
static const int DC_SMEM     = 2*DC_XC_BYTES + DC_WS_BYTES;  // 57856

__global__ __launch_bounds__(256, 2)
void deconv_kernel(const float* CK x, const float* CK b1) {
    extern __shared__ unsigned char smem_raw[];
    float (*xs0)[9][DC_X_STRIDE] = (float(*)[9][DC_X_STRIDE])smem_raw;
    float (*xs1)[9][DC_X_STRIDE] = (float(*)[9][DC_X_STRIDE])(smem_raw + DC_XC_BYTES);
    ull   (*ws)[32][4]           = (ull(*)[32][4])(smem_raw + 2*DC_XC_BYTES);

    const int tid = threadIdx.x;
    const int rt = blockIdx.x >> 1;
    const int st = blockIdx.x & 1;
    const int R0 = rt * 8, S0 = st * 32;
    const int p   = blockIdx.y >> 2;
    const int co0 = (blockIdx.y & 3) * 32;
    const int pr = p >> 1, ps = p & 1;
    const int b = blockIdx.z;

    const int cg4 = tid >> 5;          // 8 co-groups of 4
    const int pg  = tid & 31;
    const int r   = pg & 7;            // 0..7 (phase-group friendly)
    const int s8  = (pg >> 3) * 8;     // 0,8,16,24

    ull acc[4][4];
#pragma unroll
    for (int a = 0; a < 4; a++)
#pragma unroll
        for (int q = 0; q < 4; q++) acc[a][q] = 0ull;

    const int rowbase = R0 - (1 - pr);
    const int colbase = S0 - (1 - ps);

    for (int ch = 0; ch < 16; ch++) {
        const int ci0 = ch * 16;
        // x halo tile (zero padded at border); dual store: shift0 + shift1
        for (int e = tid; e < 16*9*34; e += 256) {
            int col = e % 34;
            int tmp = e / 34;
            int row = tmp % 9;
            int cc  = tmp / 9;
            int gr = rowbase + row, gc = colbase + col;
            float v = 0.f;
            if ((unsigned)gr < 64u && (unsigned)gc < 64u)
                v = x[((b*256 + ci0 + cc)*64 + gr)*64 + gc];
            xs0[cc][row][col] = v;
            if (col >= 1) xs1[cc][row][col - 1] = v;
        }
        // duplicated weight pairs (32-co slice, 128-ull rows per ci)
        {
            const ull* wsrc = (const ull*)&g_w1d[((size_t)(p*256 + ci0)*128 + co0)*8];
            ull* wdst = &ws[0][0][0];
            for (int e = tid; e < 16*128; e += 256) {
                int cc = e >> 7;
                int rest = e & 127;
                wdst[cc*128 + rest] = wsrc[cc*512 + rest];
            }
        }
        __syncthreads();

#pragma unroll 1
        for (int cc = 0; cc < 16; cc++) {
            const ulonglong2* ph0 = (const ulonglong2*)&xs0[cc][r + 1][s8];
            const ulonglong2* ph1 = (const ulonglong2*)&xs1[cc][r + 1][s8];
            const ulonglong2* pl0 = (const ulonglong2*)&xs0[cc][r    ][s8];
            const ulonglong2* pl1 = (const ulonglong2*)&xs1[cc][r    ][s8];
            ulonglong2 h0a = ph0[0], h0b = ph0[1];
            ulonglong2 h1a = ph1[0], h1b = ph1[1];
            ulonglong2 l0a = pl0[0], l0b = pl0[1];
            ulonglong2 l1a = pl1[0], l1b = pl1[1];
            ull xh0[4] = {h0a.x, h0a.y, h0b.x, h0b.y};
            ull xh1[4] = {h1a.x, h1a.y, h1b.x, h1b.y};
            ull xl0[4] = {l0a.x, l0a.y, l0b.x, l0b.y};
            ull xl1[4] = {l1a.x, l1a.y, l1b.x, l1b.y};
#pragma unroll
            for (int cg = 0; cg < 4; cg++) {
                const ulonglong2* wp = (const ulonglong2*)&ws[cc][cg4*4 + cg][0];
                ulonglong2 wa = wp[0], wb = wp[1];
#pragma unroll
                for (int q = 0; q < 4; q++) {
                    ffma2(acc[cg][q], wa.x, xh1[q]);
                    ffma2(acc[cg][q], wa.y, xh0[q]);
                    ffma2(acc[cg][q], wb.x, xl1[q]);
                    ffma2(acc[cg][q], wb.y, xl0[q]);
                }
            }
        }
        __syncthreads();
    }

    // epilogue: y = acc + b1 (stride-2 scatter into full-res y)
#pragma unroll
    for (int cg = 0; cg < 4; cg++) {
        int co = co0 + cg4*4 + cg;
        float bv = b1[co];
        int oh = 2*(R0 + r) + pr;
        float* dst = &g_y[((b*128 + co)*128 + oh)*128];
#pragma unroll
        for (int q = 0; q < 4; q++) {
            float lo, hi;
            unpack2(acc[cg][q], lo, hi);
            dst[2*(S0 + s8 + 2*q)     + ps] = lo + bv;
            dst[2*(S0 + s8 + 2*q + 1) + ps] = hi + bv;
        }
    }
}

// ---------------- stage 2a: gaussian kernel factors ----------------
__global__ __launch_bounds__(256)
void kfac_kernel(const float* CK guide) {
    const int tid = threadIdx.x;
    const int b = blockIdx.z;
    const int H0 = (blockIdx.x >> 3) * 16;
    const int W0 = (blockIdx.x & 7) * 16;
    __shared__ float gs[16][18][19];
    const int r  = tid >> 4;
    const int sc = tid & 15;
    float acc[9];
#pragma unroll
    for (int k = 0; k < 9; k++) acc[k] = 0.f;

    for (int ch = 0; ch < 8; ch++) {
        const int c0 = ch * 16;
        for (int e = tid; e < 16*18*18; e += 256) {
            int col = e % 18;
            int tmp = e / 18;
            int row = tmp % 18;
            int cc  = tmp / 18;
            int gr = H0 - 1 + row, gc = W0 - 1 + col;
            float v = 0.f;
            if ((unsigned)gr < 128u && (unsigned)gc < 128u)
                v = guide[((b*128 + c0 + cc)*128 + gr)*128 + gc];
            gs[cc][row][col] = v;
        }
        __syncthreads();
#pragma unroll 1
        for (int cc = 0; cc < 16; cc++) {
            float gc0 = gs[cc][r + 1][sc + 1];
#pragma unroll
            for (int ij = 0; ij < 9; ij++) {
                int di = ij / 3, dj = ij % 3;
                float d = gs[cc][r + di][sc + dj] - gc0;
                acc[ij] += d * d;
            }
        }
        __syncthreads();
    }
#pragma unroll
    for (int ij = 0; ij < 9; ij++)
        g_kf[((b*9 + ij)*128 + H0 + r)*128 + W0 + sc] = expf(-0.5f * acc[ij]);
}

// ---------------- stage 2b: PAC main (9-tap scaled conv, f32x2, LDS.128) ----------------
// Block: 32 co x (16x16) spatial tile. Thread: 4co x 8pos (4 f32x2 pairs) -> acc 16 ull.
// Three y copies (shift 0/1/2), row stride 20 floats, occupancy 3.
static const int PC_Y_STRIDE = 20;
static const int PC_YC_BYTES = 8*18*PC_Y_STRIDE*4;   // 5760 per copy
static const int PC_KS_BYTES = 9*16*PC_Y_STRIDE*4;   // 11520
static const int PC_WS_BYTES = 8*9*32*8;             // 18432 (ull pairs, 32 co)
static const int PC_SMEM     = 3*PC_YC_BYTES + PC_KS_BYTES + PC_WS_BYTES;  // 47232

__global__ __launch_bounds__(256, 3)
void pac_kernel(const float* CK b2, float* CK out) {
    extern __shared__ unsigned char smem_raw[];
    float* ybase0 = (float*)smem_raw;                         // shift 0
    float* ybase1 = (float*)(smem_raw + PC_YC_BYTES);         // shift 1
    float* ybase2 = (float*)(smem_raw + 2*PC_YC_BYTES);       // shift 2
    float (*ksm)[16][PC_Y_STRIDE] =
        (float(*)[16][PC_Y_STRIDE])(smem_raw + 3*PC_YC_BYTES);
    ull   (*wsm)[9][32] = (ull(*)[9][32])(smem_raw + 3*PC_YC_BYTES + PC_KS_BYTES);

    const int tid = threadIdx.x;
    const int b = blockIdx.z;
    const int co0 = blockIdx.y * 32;
    const int H0 = (blockIdx.x >> 3) * 16;
    const int W0 = (blockIdx.x & 7) * 16;

    const int cg4 = tid >> 5;          // 8 co-groups of 4
    const int pg  = tid & 31;
    const int r   = pg & 15;           // 0..15 (phase-group friendly)
    const int sc8 = (pg >> 4) * 8;     // 0,8

    // gaussian factors for tile (once)
    for (int e = tid; e < 9*256; e += 256) {
        int cc = e & 255;
        int ij = e >> 8;
        int rr = cc >> 4, col = cc & 15;
        ksm[ij][rr][col] = g_kf[((b*9 + ij)*128 + H0 + rr)*128 + W0 + col];
    }

    ull acc[4][4];
#pragma unroll
    for (int a = 0; a < 4; a++)
#pragma unroll
        for (int q = 0; q < 4; q++) acc[a][q] = 0ull;

    for (int ch = 0; ch < 16; ch++) {
        const int c0 = ch * 8;
        // y halo tile; triple store: shift 0 / 1 / 2
        for (int e = tid; e < 8*18*18; e += 256) {
            int col = e % 18;
            int tmp = e / 18;
            int row = tmp % 18;
            int cc  = tmp / 18;
            int gr = H0 - 1 + row, gc = W0 - 1 + col;
            float v = 0.f;
            if ((unsigned)gr < 128u && (unsigned)gc < 128u)
                v = g_y[((b*128 + c0 + cc)*128 + gr)*128 + gc];
            int base = (cc*18 + row) * PC_Y_STRIDE;
            ybase0[base + col] = v;
            if (col >= 1) ybase1[base + col - 1] = v;
            if (col >= 2) ybase2[base + col - 2] = v;
        }
        // duplicated weight pairs (32-co slice)
        {
            const ull* wsrc = ((const ull*)g_w2d) + (size_t)(c0*9)*128 + co0;
            for (int e = tid; e < 8*9*32; e += 256) {
                int ol = e & 31;
                int ij = (e >> 5) % 9;
                int cc = e / (9*32);
                wsm[cc][ij][ol] = wsrc[((size_t)cc*9 + ij)*128 + ol];
            }
        }
        __syncthreads();

#pragma unroll 1
        for (int ij = 0; ij < 9; ij++) {
            const int di = ij / 3, dj = ij % 3;
            const float* ysel = (dj == 0) ? ybase0 : (dj == 1) ? ybase1 : ybase2;
            const ulonglong2* kp = (const ulonglong2*)&ksm[ij][r][sc8];
            ulonglong2 k01 = kp[0], k23 = kp[1];
#pragma unroll
            for (int cc = 0; cc < 8; cc++) {
                const ulonglong2* yp =
                    (const ulonglong2*)(ysel + (cc*18 + r + di)*PC_Y_STRIDE + sc8);
                ulonglong2 ya = yp[0], yb = yp[1];
                ull t0 = mul2(ya.x, k01.x);
                ull t1 = mul2(ya.y, k01.y);
                ull t2 = mul2(yb.x, k23.x);
                ull t3 = mul2(yb.y, k23.y);
                const ulonglong2* wp = (const ulonglong2*)&wsm[cc][ij][cg4*4];
                ulonglong2 w01 = wp[0], w23 = wp[1];
                ffma2(acc[0][0], w01.x, t0); ffma2(acc[0][1], w01.x, t1);
                ffma2(acc[0][2], w01.x, t2); ffma2(acc[0][3], w01.x, t3);
                ffma2(acc[1][0], w01.y, t0); ffma2(acc[1][1], w01.y, t1);
                ffma2(acc[1][2], w01.y, t2); ffma2(acc[1][3], w01.y, t3);
                ffma2(acc[2][0], w23.x, t0); ffma2(acc[2][1], w23.x, t1);
                ffma2(acc[2][2], w23.x, t2); ffma2(acc[2][3], w23.x, t3);
                ffma2(acc[3][0], w23.y, t0); ffma2(acc[3][1], w23.y, t1);
                ffma2(acc[3][2], w23.y, t2); ffma2(acc[3][3], w23.y, t3);
            }
        }
        __syncthreads();
    }

    // epilogue: out = acc + b2 (STG.64 pairs)
#pragma unroll
    for (int cg = 0; cg < 4; cg++) {
        int co = co0 + cg4*4 + cg;
        float bv = b2[co];
        ull bvd = pack2(bv, bv);
        float* dst = &out[((size_t)(b*128 + co)*128 + H0 + r)*128 + W0 + sc8];
#pragma unroll
        for (int q = 0; q < 4; q++)
            *(ull*)(dst + 2*q) = add2(acc[cg][q], bvd);
    }
}

// ---------------- launch ----------------
extern "C" void kernel_launch(void* const* d_in, const int* in_sizes, int n_in,
                              void* d_out, int out_size) {
    const float* x     = (const float*)d_in[0];
    const float* guide = (const float*)d_in[1];
    const float* w1    = (const float*)d_in[2];
    const float* b1    = (const float*)d_in[3];
    const float* w2    = (const float*)d_in[4];
    const float* b2    = (const float*)d_in[5];
    float* out = (float*)d_out;

    cudaFuncSetAttribute(deconv_kernel, cudaFuncAttributeMaxDynamicSharedMemorySize, DC_SMEM);
    cudaFuncSetAttribute(pac_kernel,    cudaFuncAttributeMaxDynamicSharedMemorySize, PC_SMEM);

    prep_weights_kernel<<<(4*256*128*4 + 255)/256, 256>>>(w1, w2);
    deconv_kernel<<<dim3(16, 16, 4), 256, DC_SMEM>>>(x, b1);
    kfac_kernel<<<dim3(64, 1, 4), 256>>>(guide);
    pac_kernel<<<dim3(64, 4, 4), 256, PC_SMEM>>>(b2, out);
}

// round 12
// speedup vs baseline: 1.4917x; 1.4917x over previous
#include <cuda_runtime.h>
#include <cuda_bf16.h>
#include <cstdint>

#define CK __restrict__
typedef unsigned long long ull;

// ---------------- f32x2 helpers (deconv SIMT path) ----------------
__device__ __forceinline__ void unpack2(ull v, float& lo, float& hi) {
    asm("mov.b64 {%0, %1}, %2;" : "=f"(lo), "=f"(hi) : "l"(v));
}
__device__ __forceinline__ void ffma2(ull& d, ull a, ull b) {
    asm("fma.rn.f32x2 %0, %1, %2, %0;" : "+l"(d) : "l"(a), "l"(b));
}

// ---------------- bf16 helpers ----------------
// pack two fp32 -> bf16x2 (first arg -> low 16 bits)
__device__ __forceinline__ uint32_t bf16x2_of(float lo, float hi) {
    uint32_t r;
    asm("cvt.rn.bf16x2.f32 %0, %1, %2;" : "=r"(r) : "f"(hi), "f"(lo));
    return r;
}
// residual pair: (x,y) minus the bf16 values packed in hp
__device__ __forceinline__ uint32_t resid2(uint32_t hp, float x, float y) {
    float hx = __uint_as_float(hp << 16);
    float hy = __uint_as_float(hp & 0xffff0000u);
    return bf16x2_of(x - hx, y - hy);
}
// m16n8k16 row.col bf16 MMA, D+=A*B (fp32 accum)
__device__ __forceinline__ void mma16816(float* d, uint32_t a0, uint32_t a1,
                                         uint32_t a2, uint32_t a3,
                                         uint32_t b0, uint32_t b1) {
    asm volatile(
        "mma.sync.aligned.m16n8k16.row.col.f32.bf16.bf16.f32 "
        "{%0,%1,%2,%3}, {%4,%5,%6,%7}, {%8,%9}, {%0,%1,%2,%3};"
        : "+f"(d[0]), "+f"(d[1]), "+f"(d[2]), "+f"(d[3])
        : "r"(a0), "r"(a1), "r"(a2), "r"(a3), "r"(b0), "r"(b1));
}

// ---------------- scratch ----------------
__device__ float g_y [4*128*128*128];
__device__ float g_kf[4*9*128*128];
__device__ __align__(16) float g_w1d[4*256*128*4*2];
// w2 bf16 pair-packed for B fragments: [ch(2)][ij(9)][kk(32)][co(128)] uint32 = {w[2kk],w[2kk+1]}
__device__ __align__(16) uint32_t g_w2ph[2*9*32*128];
__device__ __align__(16) uint32_t g_w2pl[2*9*32*128];

// ---------------- weight prep ----------------
__global__ void prep_weights_kernel(const float* CK w1, const float* CK w2) {
    int idx = blockIdx.x * blockDim.x + threadIdx.x;
    const int n1 = 4*256*128*4;
    if (idx < n1) {
        int t  = idx & 3;
        int co = (idx >> 2) & 127;
        int ci = (idx >> 9) & 255;
        int p  = idx >> 17;
        int pr = p >> 1, ps = p & 1;
        int th = t >> 1, tw = t & 1;
        int kh = 2*th + 1 - pr;
        int kw = 2*tw + 1 - ps;
        float v = w1[((ci*128 + co)*4 + kh)*4 + kw];
        g_w1d[idx*2]   = v;
        g_w1d[idx*2+1] = v;
    }
    const int n2 = 128*9*128;
    if (idx < n2) {
        int o  = idx & 127;
        int ij = (idx >> 7) % 9;
        int c  = idx / (9*128);
        int i = ij / 3, j = ij % 3;
        float v = w2[((c*128 + o)*3 + (2 - i))*3 + (2 - j)];  // wk[o,c,i,j]
        __nv_bfloat16 hb = __float2bfloat16(v);
        float hv = __bfloat162float(hb);
        __nv_bfloat16 lb = __float2bfloat16(v - hv);
        int ch = c >> 6, rem = c & 63, kk = rem >> 1, par = rem & 1;
        size_t word = (((size_t)ch*9 + ij)*32 + kk)*128 + o;
        ((unsigned short*)g_w2ph)[word*2 + par] = __bfloat16_as_ushort(hb);
        ((unsigned short*)g_w2pl)[word*2 + par] = __bfloat16_as_ushort(lb);
    }
}

// ---------------- stage 1: conv_transpose (f32x2 SIMT) ----------------
static const int DC_X_STRIDE = 36;
static const int DC_XC_BYTES = 16*9*DC_X_STRIDE*4;
static const int DC_SMEM     = 2*DC_XC_BYTES + 16*64*4*8;

__global__ __launch_bounds__(256, 2)
void deconv_kernel(const float* CK x, const float* CK b1) {
    extern __shared__ unsigned char smem_raw[];
    float (*xs0)[9][DC_X_STRIDE] = (float(*)[9][DC_X_STRIDE])smem_raw;
    float (*xs1)[9][DC_X_STRIDE] = (float(*)[9][DC_X_STRIDE])(smem_raw + DC_XC_BYTES);
    ull   (*ws)[64][4]           = (ull(*)[64][4])(smem_raw + 2*DC_XC_BYTES);

    const int tid = threadIdx.x;
    const int rt = blockIdx.x >> 1;
    const int st = blockIdx.x & 1;
    const int R0 = rt * 8, S0 = st * 32;
    const int p   = blockIdx.y >> 1;
    const int co0 = (blockIdx.y & 1) * 64;
    const int pr = p >> 1, ps = p & 1;
    const int b = blockIdx.z;

    const int cg8 = tid >> 5;
    const int pg  = tid & 31;
    const int r   = pg & 7;
    const int s8  = (pg >> 3) * 8;

    ull acc[8][4];
#pragma unroll
    for (int a = 0; a < 8; a++)
#pragma unroll
        for (int q = 0; q < 4; q++) acc[a][q] = 0ull;

    const int rowbase = R0 - (1 - pr);
    const int colbase = S0 - (1 - ps);

    for (int ch = 0; ch < 16; ch++) {
        const int ci0 = ch * 16;
        for (int e = tid; e < 16*9*34; e += 256) {
            int col = e % 34;
            int tmp = e / 34;
            int row = tmp % 9;
            int cc  = tmp / 9;
            int gr = rowbase + row, gc = colbase + col;
            float v = 0.f;
            if ((unsigned)gr < 64u && (unsigned)gc < 64u)
                v = x[((b*256 + ci0 + cc)*64 + gr)*64 + gc];
            xs0[cc][row][col] = v;
            if (col >= 1) xs1[cc][row][col - 1] = v;
        }
        {
            const ull* wsrc = (const ull*)&g_w1d[((size_t)(p*256 + ci0)*128 + co0)*8];
            ull* wdst = &ws[0][0][0];
            for (int e = tid; e < 16*256; e += 256) {
                int cc = e >> 8;
                int rest = e & 255;
                wdst[cc*256 + rest] = wsrc[cc*512 + rest];
            }
        }
        __syncthreads();

#pragma unroll 1
        for (int cc = 0; cc < 16; cc++) {
            const ulonglong2* ph0 = (const ulonglong2*)&xs0[cc][r + 1][s8];
            const ulonglong2* ph1 = (const ulonglong2*)&xs1[cc][r + 1][s8];
            const ulonglong2* pl0 = (const ulonglong2*)&xs0[cc][r    ][s8];
            const ulonglong2* pl1 = (const ulonglong2*)&xs1[cc][r    ][s8];
            ulonglong2 h0a = ph0[0], h0b = ph0[1];
            ulonglong2 h1a = ph1[0], h1b = ph1[1];
            ulonglong2 l0a = pl0[0], l0b = pl0[1];
            ulonglong2 l1a = pl1[0], l1b = pl1[1];
            ull xh0[4] = {h0a.x, h0a.y, h0b.x, h0b.y};
            ull xh1[4] = {h1a.x, h1a.y, h1b.x, h1b.y};
            ull xl0[4] = {l0a.x, l0a.y, l0b.x, l0b.y};
            ull xl1[4] = {l1a.x, l1a.y, l1b.x, l1b.y};
#pragma unroll
            for (int cg = 0; cg < 8; cg++) {
                const ulonglong2* wp = (const ulonglong2*)&ws[cc][cg8*8 + cg][0];
                ulonglong2 wa = wp[0], wb = wp[1];
#pragma unroll
                for (int q = 0; q < 4; q++) {
                    ffma2(acc[cg][q], wa.x, xh1[q]);
                    ffma2(acc[cg][q], wa.y, xh0[q]);
                    ffma2(acc[cg][q], wb.x, xl1[q]);
                    ffma2(acc[cg][q], wb.y, xl0[q]);
                }
            }
        }
        __syncthreads();
    }

#pragma unroll
    for (int cg = 0; cg < 8; cg++) {
        int co = co0 + cg8*8 + cg;
        float bv = b1[co];
        int oh = 2*(R0 + r) + pr;
        float* dst = &g_y[((b*128 + co)*128 + oh)*128];
#pragma unroll
        for (int q = 0; q < 4; q++) {
            float lo, hi;
            unpack2(acc[cg][q], lo, hi);
            dst[2*(S0 + s8 + 2*q)     + ps] = lo + bv;
            dst[2*(S0 + s8 + 2*q + 1) + ps] = hi + bv;
        }
    }
}

// ---------------- stage 2a: gaussian kernel factors ----------------
__global__ __launch_bounds__(256)
void kfac_kernel(const float* CK guide) {
    const int tid = threadIdx.x;
    const int b = blockIdx.z;
    const int H0 = (blockIdx.x >> 3) * 16;
    const int W0 = (blockIdx.x & 7) * 16;
    __shared__ float gs[16][18][19];
    const int r  = tid >> 4;
    const int sc = tid & 15;
    float acc[9];
#pragma unroll
    for (int k = 0; k < 9; k++) acc[k] = 0.f;

    for (int ch = 0; ch < 8; ch++) {
        const int c0 = ch * 16;
        for (int e = tid; e < 16*18*18; e += 256) {
            int col = e % 18;
            int tmp = e / 18;
            int row = tmp % 18;
            int cc  = tmp / 18;
            int gr = H0 - 1 + row, gc = W0 - 1 + col;
            float v = 0.f;
            if ((unsigned)gr < 128u && (unsigned)gc < 128u)
                v = guide[((b*128 + c0 + cc)*128 + gr)*128 + gc];
            gs[cc][row][col] = v;
        }
        __syncthreads();
#pragma unroll 1
        for (int cc = 0; cc < 16; cc++) {
            float gc0 = gs[cc][r + 1][sc + 1];
#pragma unroll
            for (int ij = 0; ij < 9; ij++) {
                int di = ij / 3, dj = ij % 3;
                float d = gs[cc][r + di][sc + dj] - gc0;
                acc[ij] += d * d;
            }
        }
        __syncthreads();
    }
#pragma unroll
    for (int ij = 0; ij < 9; ij++)
        g_kf[((b*9 + ij)*128 + H0 + r)*128 + W0 + sc] = expf(-0.5f * acc[ij]);
}

// ---------------- stage 2b: PAC via mma.sync bf16 split (3 passes) ----------------
// CTA: 8x16 spatial tile (M=128 positions) x N=128 co. 8 warps: 4 M-warps x 2 N-warps.
// Warp tile: 32M x 64N. K = 2 ch-halves x 9 ij x 64 c.
static const int PT_B2S  = 0;                 // 128 floats
static const int PT_KS   = 512;               // 9*128 floats = 4608
static const int PT_Y    = 5120;              // 64 ch * 212 floats = 54272
static const int PT_WH   = 59392;             // 32*128 uint32 = 16384
static const int PT_WL   = 75776;             // 16384
static const int PT_SMEM = 92160;
static const int YCH = 212;                   // channel stride (floats); rows: 10 x 21

__global__ __launch_bounds__(256, 2)
void pac_tensor_kernel(const float* CK b2, float* CK out) {
    extern __shared__ unsigned char smem_raw[];
    float*    b2s  = (float*)(smem_raw + PT_B2S);
    float*    ksm  = (float*)(smem_raw + PT_KS);
    float*    ys   = (float*)(smem_raw + PT_Y);
    uint32_t* wsmh = (uint32_t*)(smem_raw + PT_WH);
    uint32_t* wsml = (uint32_t*)(smem_raw + PT_WL);

    const int tid  = threadIdx.x;
    const int wid  = tid >> 5;
    const int lane = tid & 31;
    const int g    = lane >> 2;        // 0..7
    const int t    = lane & 3;         // 0..3
    const int wm   = wid & 3;          // M-warp 0..3
    const int wn   = wid >> 2;         // N-warp 0..1
    const int bb = blockIdx.z;
    const int H0 = (blockIdx.x >> 3) * 8;
    const int W0 = (blockIdx.x & 7) * 16;

    // one-time tile loads
    for (int e = tid; e < 1152; e += 256) {
        int ij = e >> 7, mm = e & 127;
        ksm[e] = g_kf[((bb*9 + ij)*128 + H0 + (mm >> 4))*128 + W0 + (mm & 15)];
    }
    if (tid < 128) b2s[tid] = b2[tid];

    float acc[2][8][4];
#pragma unroll
    for (int a = 0; a < 2; a++)
#pragma unroll
        for (int n = 0; n < 8; n++)
#pragma unroll
            for (int q = 0; q < 4; q++) acc[a][n][q] = 0.f;

    for (int ch = 0; ch < 2; ch++) {
        __syncthreads();   // previous readers of ys done
        // y half tile: 64 channels x rows [H0-1, H0+8] x cols [W0-1, W0+16]
        for (int e = tid; e < 64*10*18; e += 256) {
            int col = e % 18;
            int tmp = e / 18;
            int row = tmp % 10;
            int c   = tmp / 10;
            int gr = H0 - 1 + row, gc = W0 - 1 + col;
            float v = 0.f;
            if ((unsigned)gr < 128u && (unsigned)gc < 128u)
                v = g_y[((bb*128 + ch*64 + c)*128 + gr)*128 + gc];
            ys[c*YCH + row*21 + col] = v;
        }

        for (int ij = 0; ij < 9; ij++) {
            const int di = ij / 3, dj = ij % 3;
            __syncthreads();   // previous wsm readers done (and ys stores visible)
            // stage B chunk (ch, ij): 4096 uint32 hi + lo
            {
                const uint4* hsrc = (const uint4*)(g_w2ph + ((size_t)ch*9 + ij)*4096);
                const uint4* lsrc = (const uint4*)(g_w2pl + ((size_t)ch*9 + ij)*4096);
#pragma unroll
                for (int i = 0; i < 4; i++) {
                    ((uint4*)wsmh)[tid + i*256] = hsrc[tid + i*256];
                    ((uint4*)wsml)[tid + i*256] = lsrc[tid + i*256];
                }
            }
            __syncthreads();

#pragma unroll 1
            for (int kc = 0; kc < 4; kc++) {
                const int cb = kc*16 + 2*t;
                uint32_t ah[2][4], al[2][4];
#pragma unroll
                for (int mt = 0; mt < 2; mt++) {
                    const int prr = wm*2 + mt;
                    const int mb = wm*32 + mt*16;
                    float k1 = ksm[ij*128 + mb + g];
                    float k2 = ksm[ij*128 + mb + g + 8];
                    const float* yb = ys + (prr + di)*21 + dj;
                    float t1a = yb[(cb    )*YCH + g] * k1;
                    float t1b = yb[(cb + 1)*YCH + g] * k1;
                    float t1c = yb[(cb + 8)*YCH + g] * k1;
                    float t1d = yb[(cb + 9)*YCH + g] * k1;
                    float t2a = yb[(cb    )*YCH + g + 8] * k2;
                    float t2b = yb[(cb + 1)*YCH + g + 8] * k2;
                    float t2c = yb[(cb + 8)*YCH + g + 8] * k2;
                    float t2d = yb[(cb + 9)*YCH + g + 8] * k2;
                    ah[mt][0] = bf16x2_of(t1a, t1b);
                    ah[mt][1] = bf16x2_of(t2a, t2b);
                    ah[mt][2] = bf16x2_of(t1c, t1d);
                    ah[mt][3] = bf16x2_of(t2c, t2d);
                    al[mt][0] = resid2(ah[mt][0], t1a, t1b);
                    al[mt][1] = resid2(ah[mt][1], t2a, t2b);
                    al[mt][2] = resid2(ah[mt][2], t1c, t1d);
                    al[mt][3] = resid2(ah[mt][3], t2c, t2d);
                }
#pragma unroll
                for (int nt = 0; nt < 8; nt++) {
                    const int n = wn*64 + nt*8 + g;
                    uint32_t bh0 = wsmh[(kc*8 + t    )*128 + n];
                    uint32_t bh1 = wsmh[(kc*8 + t + 4)*128 + n];
                    uint32_t bl0 = wsml[(kc*8 + t    )*128 + n];
                    uint32_t bl1 = wsml[(kc*8 + t + 4)*128 + n];
                    mma16816(acc[0][nt], ah[0][0], ah[0][1], ah[0][2], ah[0][3], bh0, bh1);
                    mma16816(acc[1][nt], ah[1][0], ah[1][1], ah[1][2], ah[1][3], bh0, bh1);
                    mma16816(acc[0][nt], al[0][0], al[0][1], al[0][2], al[0][3], bh0, bh1);
                    mma16816(acc[1][nt], al[1][0], al[1][1], al[1][2], al[1][3], bh0, bh1);
                    mma16816(acc[0][nt], ah[0][0], ah[0][1], ah[0][2], ah[0][3], bl0, bl1);
                    mma16816(acc[1][nt], ah[1][0], ah[1][1], ah[1][2], ah[1][3], bl0, bl1);
                }
            }
        }
    }

    // epilogue: D fragment c0,c1 -> (row g, co 2t,2t+1); c2,c3 -> (row g+8)
#pragma unroll
    for (int mt = 0; mt < 2; mt++) {
        const int prr = wm*2 + mt;
#pragma unroll
        for (int nt = 0; nt < 8; nt++) {
            int co = wn*64 + nt*8 + 2*t;
            float bv0 = b2s[co], bv1 = b2s[co + 1];
            size_t base = ((size_t)(bb*128 + co)*128 + H0 + prr)*128 + W0;
            out[base + g]            = acc[mt][nt][0] + bv0;
            out[base + 16384 + g]    = acc[mt][nt][1] + bv1;
            out[base + g + 8]        = acc[mt][nt][2] + bv0;
            out[base + 16384 + g + 8]= acc[mt][nt][3] + bv1;
        }
    }
}

// ---------------- launch ----------------
extern "C" void kernel_launch(void* const* d_in, const int* in_sizes, int n_in,
                              void* d_out, int out_size) {
    const float* x     = (const float*)d_in[0];
    const float* guide = (const float*)d_in[1];
    const float* w1    = (const float*)d_in[2];
    const float* b1    = (const float*)d_in[3];
    const float* w2    = (const float*)d_in[4];
    const float* b2    = (const float*)d_in[5];
    float* out = (float*)d_out;

    cudaFuncSetAttribute(deconv_kernel,     cudaFuncAttributeMaxDynamicSharedMemorySize, DC_SMEM);
    cudaFuncSetAttribute(pac_tensor_kernel, cudaFuncAttributeMaxDynamicSharedMemorySize, PT_SMEM);

    prep_weights_kernel<<<(4*256*128*4 + 255)/256, 256>>>(w1, w2);
    deconv_kernel<<<dim3(16, 8, 4), 256, DC_SMEM>>>(x, b1);
    kfac_kernel<<<dim3(64, 1, 4), 256>>>(guide);
    pac_tensor_kernel<<<dim3(128, 1, 4), 256, PT_SMEM>>>(b2, out);
}